// round 12
// baseline (speedup 1.0000x reference)
#include <cuda_runtime.h>
#include <cuda_fp16.h>
#include <math.h>
#include <stdint.h>

// ---------------- problem dims (fixed) ----------------
#define T_STEPS   4
#define NODE_NUM  10000
#define NUM_NODES 50000
#define E_DIM     256
#define H_DIM     512
#define C_DIM     128
#define U_DIM     256
#define ROWS      (T_STEPS * NODE_NUM)   // 40000
#define LN_EPS    1e-5f
#define MBLK64    (ROWS / 64)            // 625 (exact)

// ---------------- scratch (__device__ globals) ----------------
__device__ float g_S[(size_t)T_STEPS * NUM_NODES * E_DIM];
__device__ int   g_cnt[T_STEPS * NUM_NODES];
__device__ int   g_tick[ROWS];
__device__ __half g_A0[(size_t)ROWS * E_DIM];
__device__ __half g_H1[(size_t)ROWS * H_DIM];
__device__ __half g_G [(size_t)ROWS * C_DIM];
__device__ __half g_H2[(size_t)ROWS * U_DIM];
// transposed + split fp16 weights, [N][K]
__device__ __half g_w1dh[H_DIM * E_DIM], g_w1dl[H_DIM * E_DIM];
__device__ __half g_w2dh[C_DIM * H_DIM], g_w2dl[C_DIM * H_DIM];
__device__ __half g_w1uh[U_DIM * C_DIM], g_w1ul[U_DIM * C_DIM];
__device__ __half g_w2uh[E_DIM * U_DIM], g_w2ul[E_DIM * U_DIM];

// ---------------- helpers ----------------
static __device__ __forceinline__ uint32_t smem_u32(const void* p) {
    uint32_t a;
    asm("{ .reg .u64 t; cvta.to.shared.u64 t, %1; cvt.u32.u64 %0, t; }" : "=r"(a) : "l"(p));
    return a;
}

static __device__ __forceinline__ float gelu_exact(float v) {
    return 0.5f * v * (1.0f + erff(v * 0.70710678118654752f));
}

#define CP_ASYNC16_U(dst, src) \
    asm volatile("cp.async.cg.shared.global [%0], [%1], 16;" \
                 :: "r"(dst), "l"(src) : "memory")
#define CP_COMMIT() asm volatile("cp.async.commit_group;" ::: "memory")
#define CP_WAIT1()  asm volatile("cp.async.wait_group 1;" ::: "memory")

#define LDMATRIX_X4(r0, r1, r2, r3, addr) \
    asm volatile("ldmatrix.sync.aligned.m8n8.x4.shared.b16 {%0,%1,%2,%3}, [%4];" \
                 : "=r"(r0), "=r"(r1), "=r"(r2), "=r"(r3) : "r"(addr))

#define MMA16816(c0, c1, c2, c3, a0, a1, a2, a3, b0, b1) \
    asm volatile("mma.sync.aligned.m16n8k16.row.col.f32.f16.f16.f32 " \
                 "{%0,%1,%2,%3}, {%4,%5,%6,%7}, {%8,%9}, {%0,%1,%2,%3};" \
                 : "+f"(c0), "+f"(c1), "+f"(c2), "+f"(c3) \
                 : "r"(a0), "r"(a1), "r"(a2), "r"(a3), "r"(b0), "r"(b1))

// ---------------- prep: ALL four weights in one launch ----------------
// Each 32x32 tile: coalesced transpose + fp16 split. 288 blocks total.
__global__ void k_wsplit_all(const float* __restrict__ W1d, const float* __restrict__ W2d,
                             const float* __restrict__ W1u, const float* __restrict__ W2u) {
    __shared__ float tile[32][33];
    int b = blockIdx.x;
    const float* W; __half *hi, *lo; int K, N, nb, kb;
    if (b < 128) {          // W1d: K=256, N=512 -> grid 16 x 8
        W = W1d; hi = g_w1dh; lo = g_w1dl; K = E_DIM; N = H_DIM;
        nb = (b & 15) * 32; kb = (b >> 4) * 32;
    } else if (b < 192) {   // W2d: K=512, N=128 -> grid 4 x 16
        b -= 128; W = W2d; hi = g_w2dh; lo = g_w2dl; K = H_DIM; N = C_DIM;
        nb = (b & 3) * 32; kb = (b >> 2) * 32;
    } else if (b < 224) {   // W1u: K=128, N=256 -> grid 8 x 4
        b -= 192; W = W1u; hi = g_w1uh; lo = g_w1ul; K = C_DIM; N = U_DIM;
        nb = (b & 7) * 32; kb = (b >> 3) * 32;
    } else {                // W2u: K=256, N=256 -> grid 8 x 8
        b -= 224; W = W2u; hi = g_w2uh; lo = g_w2ul; K = U_DIM; N = E_DIM;
        nb = (b & 7) * 32; kb = (b >> 3) * 32;
    }
    int tx = threadIdx.x, ty = threadIdx.y;
    #pragma unroll
    for (int i = 0; i < 32; i += 8)
        tile[ty + i][tx] = W[(size_t)(kb + ty + i) * N + nb + tx];
    __syncthreads();
    #pragma unroll
    for (int i = 0; i < 32; i += 8) {
        int n = nb + ty + i, k = kb + tx;
        float v = tile[tx][ty + i];
        __half h = __float2half_rn(v);
        hi[(size_t)n * K + k] = h;
        lo[(size_t)n * K + k] = __float2half_rn(v - __half2float(h));
    }
}

// ---------------- front-end (duplicate-aware) ----------------
__global__ void k_clr() {
    int i = blockIdx.x * 256 + threadIdx.x;
    if (i < T_STEPS * NUM_NODES) g_cnt[i] = 0;
}

__global__ void k_count(const int* __restrict__ idx) {
    int r = blockIdx.x * 256 + threadIdx.x;
    if (r >= ROWS) return;
    int t = r / NODE_NUM;
    g_tick[r] = atomicAdd(&g_cnt[t * NUM_NODES + idx[r]], 1);
}

__global__ void k_zero_dup(const int* __restrict__ idx) {
    int r = blockIdx.x * 8 + (threadIdx.x >> 5);
    if (r >= ROWS) return;
    int t = r / NODE_NUM;
    int node = idx[r];
    if (g_cnt[t * NUM_NODES + node] < 2 || g_tick[r] != 0) return;
    int lane = threadIdx.x & 31;
    float4* p = (float4*)&g_S[((size_t)t * NUM_NODES + node) * E_DIM];
    float4 z = make_float4(0.f, 0.f, 0.f, 0.f);
    p[lane] = z; p[lane + 32] = z;
}

__global__ void k_scat_dup(const float* __restrict__ x, const int* __restrict__ idx) {
    int r = blockIdx.x * 8 + (threadIdx.x >> 5);
    if (r >= ROWS) return;
    int t = r / NODE_NUM;
    int node = idx[r];
    if (g_cnt[t * NUM_NODES + node] < 2) return;
    int lane = threadIdx.x & 31;
    float* dst = &g_S[((size_t)t * NUM_NODES + node) * E_DIM];
    const float* src = x + (size_t)r * E_DIM;
    #pragma unroll
    for (int j = 0; j < 8; j++)
        atomicAdd(dst + lane + j * 32, src[lane + j * 32]);
}

// gather + broadcast-add + LN(256) -> fp16 A0
__global__ void k_gather_ln(const float* __restrict__ x, const float* __restrict__ bx,
                            const int* __restrict__ idx,
                            const float* __restrict__ sc, const float* __restrict__ bi) {
    int r = blockIdx.x * 8 + (threadIdx.x >> 5);
    if (r >= ROWS) return;
    int lane = threadIdx.x & 31;
    int t = r / NODE_NUM;
    int node = idx[r];
    const float* srow = (g_cnt[t * NUM_NODES + node] < 2)
                      ? (x + (size_t)r * E_DIM)
                      : &g_S[((size_t)t * NUM_NODES + node) * E_DIM];
    const float* brow = bx + (size_t)node * E_DIM;
    float4 a0 = *(const float4*)(srow + lane * 4);
    float4 a1 = *(const float4*)(srow + 128 + lane * 4);
    float4 b0 = *(const float4*)(brow + lane * 4);
    float4 b1 = *(const float4*)(brow + 128 + lane * 4);
    float v[8] = { a0.x + b0.x, a0.y + b0.y, a0.z + b0.z, a0.w + b0.w,
                   a1.x + b1.x, a1.y + b1.y, a1.z + b1.z, a1.w + b1.w };
    float s1 = 0.f, s2 = 0.f;
    #pragma unroll
    for (int j = 0; j < 8; j++) { s1 += v[j]; s2 += v[j] * v[j]; }
    #pragma unroll
    for (int o = 16; o > 0; o >>= 1) {
        s1 += __shfl_xor_sync(0xffffffffu, s1, o);
        s2 += __shfl_xor_sync(0xffffffffu, s2, o);
    }
    float mu = s1 * (1.f / 256.f);
    float rs = rsqrtf(s2 * (1.f / 256.f) - mu * mu + LN_EPS);
    #pragma unroll
    for (int half_i = 0; half_i < 2; half_i++) {
        #pragma unroll
        for (int j = 0; j < 2; j++) {
            int c = half_i * 128 + lane * 4 + j * 2;
            float o0 = (v[half_i * 4 + j * 2 + 0] - mu) * rs * sc[c]     + bi[c];
            float o1 = (v[half_i * 4 + j * 2 + 1] - mu) * rs * sc[c + 1] + bi[c + 1];
            *(__half2*)&g_A0[(size_t)r * E_DIM + c] = __floats2half2_rn(o0, o1);
        }
    }
}

// ---------------- mma.sync fp16 GEMM, split-B (K'=2K), block 64x128 ----------------
// 8 warps (2m x 4n), warp tile 32x32. M must be a multiple of 64 (40000 = 625*64).
// EPI: 1 = bias+GELU -> fp16; 2 = bias -> fp32; 3 = bias+LN -> fp16 (N==128)
#define ROWB 144                    // padded smem row stride (bytes)
#define A_BYTES (64 * ROWB)         // 9216
#define STG_BYTES (192 * ROWB)      // A(64) + B(128) rows = 27648
#define LNPAD 132

template<int EPI>
__global__ void __launch_bounds__(256, 2) mma_gemm(
    const __half* __restrict__ A,
    const __half* __restrict__ Bhi, const __half* __restrict__ Blo,
    const float* __restrict__ bias,
    const float* __restrict__ lns, const float* __restrict__ lnb,
    __half* __restrict__ Ch, float* __restrict__ Cf,
    int M, int N, int K)
{
    extern __shared__ char smem[];
    const uint32_t sbase = smem_u32(smem);
    const int t = threadIdx.x, wid = t >> 5, lane = t & 31;
    const int wm = wid >> 2, wn = wid & 3;       // 2 x 4 warps
    const int g = lane >> 2, tig = lane & 3;
    const int quad = lane >> 3, qr = lane & 7;
    const int bm = blockIdx.y * 64, bn = blockIdx.x * 128;
    const int kc = K >> 6;
    const int nst = 2 * kc;

    const int lrow = t >> 3, lc = t & 7;

    auto load_stage = [&](int st) {
        int s = st % 3;
        int grp = st / kc;
        int kk = (st - grp * kc) << 6;
        const __half* As = A + kk;
        const __half* Bs = (grp ? Blo : Bhi) + kk;
        uint32_t Ab = sbase + s * STG_BYTES;
        uint32_t Bb = Ab + A_BYTES;
        #pragma unroll
        for (int i = 0; i < 2; i++) {           // A: 64 rows
            int row = i * 32 + lrow;
            const __half* src = As + (size_t)(bm + row) * K + lc * 8;
            CP_ASYNC16_U(Ab + row * ROWB + lc * 16, src);
        }
        #pragma unroll
        for (int i = 0; i < 4; i++) {           // B: 128 rows
            int row = i * 32 + lrow;
            const __half* src = Bs + (size_t)(bn + row) * K + lc * 8;
            CP_ASYNC16_U(Bb + row * ROWB + lc * 16, src);
        }
    };

    float acc[2][4][4];
    #pragma unroll
    for (int a = 0; a < 2; a++)
        #pragma unroll
        for (int b = 0; b < 4; b++)
            #pragma unroll
            for (int c = 0; c < 4; c++) acc[a][b][c] = 0.f;

    load_stage(0); CP_COMMIT();
    load_stage(1); CP_COMMIT();

    for (int st = 0; st < nst; ++st) {
        CP_WAIT1();
        __syncthreads();
        if (st + 2 < nst) load_stage(st + 2);
        CP_COMMIT();
        int s = st % 3;
        uint32_t Ab = sbase + s * STG_BYTES;
        uint32_t Bb = Ab + A_BYTES;
        #pragma unroll
        for (int ks = 0; ks < 4; ks++) {
            int ch = ks * 2 + (quad >> 1);
            uint32_t a[2][4], b[2][4];
            #pragma unroll
            for (int mt = 0; mt < 2; mt++) {
                uint32_t ad = Ab + (uint32_t)(wm * 32 + mt * 16 + (quad & 1) * 8 + qr) * ROWB + ch * 16;
                LDMATRIX_X4(a[mt][0], a[mt][1], a[mt][2], a[mt][3], ad);
            }
            #pragma unroll
            for (int np = 0; np < 2; np++) {
                uint32_t ad = Bb + (uint32_t)(wn * 32 + np * 16 + (quad & 1) * 8 + qr) * ROWB + ch * 16;
                LDMATRIX_X4(b[np][0], b[np][1], b[np][2], b[np][3], ad);
            }
            #pragma unroll
            for (int mt = 0; mt < 2; mt++)
                #pragma unroll
                for (int nt = 0; nt < 4; nt++)
                    MMA16816(acc[mt][nt][0], acc[mt][nt][1], acc[mt][nt][2], acc[mt][nt][3],
                             a[mt][0], a[mt][1], a[mt][2], a[mt][3],
                             b[nt >> 1][nt & 1], b[nt >> 1][2 + (nt & 1)]);
        }
    }

    if (EPI == 3) {
        // ---- fused bias + LayerNorm(128) -> fp16 out (64 rows) ----
        float* sf = (float*)smem;   // [64][LNPAD]
        __syncthreads();
        #pragma unroll
        for (int mt = 0; mt < 2; mt++) {
            int lr0 = wm * 32 + mt * 16 + g;
            #pragma unroll
            for (int nt = 0; nt < 4; nt++) {
                int col = wn * 32 + nt * 8 + tig * 2;
                float bz0 = bias[col], bz1 = bias[col + 1];
                sf[lr0 * LNPAD + col]           = acc[mt][nt][0] + bz0;
                sf[lr0 * LNPAD + col + 1]       = acc[mt][nt][1] + bz1;
                sf[(lr0 + 8) * LNPAD + col]     = acc[mt][nt][2] + bz0;
                sf[(lr0 + 8) * LNPAD + col + 1] = acc[mt][nt][3] + bz1;
            }
        }
        __syncthreads();
        #pragma unroll
        for (int rr = 0; rr < 8; rr++) {
            int lr = wid * 8 + rr;
            int grow = bm + lr;
            float v[4];
            #pragma unroll
            for (int j = 0; j < 4; j++) v[j] = sf[lr * LNPAD + lane * 4 + j];
            float s1 = v[0] + v[1] + v[2] + v[3];
            float s2 = v[0]*v[0] + v[1]*v[1] + v[2]*v[2] + v[3]*v[3];
            #pragma unroll
            for (int o = 16; o > 0; o >>= 1) {
                s1 += __shfl_xor_sync(0xffffffffu, s1, o);
                s2 += __shfl_xor_sync(0xffffffffu, s2, o);
            }
            float mu = s1 * (1.f / 128.f);
            float rs = rsqrtf(s2 * (1.f / 128.f) - mu * mu + LN_EPS);
            #pragma unroll
            for (int j = 0; j < 2; j++) {
                int c = lane * 4 + j * 2;
                float o0 = (v[j * 2 + 0] - mu) * rs * lns[c]     + lnb[c];
                float o1 = (v[j * 2 + 1] - mu) * rs * lns[c + 1] + lnb[c + 1];
                *(__half2*)&Ch[(size_t)grow * C_DIM + c] = __floats2half2_rn(o0, o1);
            }
        }
    } else {
        #pragma unroll
        for (int mt = 0; mt < 2; mt++) {
            int r0 = bm + wm * 32 + mt * 16 + g;
            int r1 = r0 + 8;
            #pragma unroll
            for (int nt = 0; nt < 4; nt++) {
                int col = bn + wn * 32 + nt * 8 + tig * 2;
                float bz0 = bias[col], bz1 = bias[col + 1];
                float v0 = acc[mt][nt][0] + bz0, v1 = acc[mt][nt][1] + bz1;
                float v2 = acc[mt][nt][2] + bz0, v3 = acc[mt][nt][3] + bz1;
                if (EPI == 1) {
                    v0 = gelu_exact(v0); v1 = gelu_exact(v1);
                    v2 = gelu_exact(v2); v3 = gelu_exact(v3);
                }
                if (EPI == 2) {
                    *(float2*)&Cf[(size_t)r0 * N + col] = make_float2(v0, v1);
                    *(float2*)&Cf[(size_t)r1 * N + col] = make_float2(v2, v3);
                } else {
                    *(__half2*)&Ch[(size_t)r0 * N + col] = __floats2half2_rn(v0, v1);
                    *(__half2*)&Ch[(size_t)r1 * N + col] = __floats2half2_rn(v2, v3);
                }
            }
        }
    }
}

// ---------------- launcher ----------------
extern "C" void kernel_launch(void* const* d_in, const int* in_sizes, int n_in,
                              void* d_out, int out_size) {
    (void)in_sizes; (void)n_in; (void)out_size;
    const float* x          = (const float*)d_in[0];
    const float* batched_x  = (const float*)d_in[1];
    const int*   indices    = (const int*)  d_in[2];
    const float* ln_d_scale = (const float*)d_in[3];
    const float* ln_d_bias  = (const float*)d_in[4];
    const float* W1_d       = (const float*)d_in[5];
    const float* b1_d       = (const float*)d_in[6];
    const float* W2_d       = (const float*)d_in[7];
    const float* b2_d       = (const float*)d_in[8];
    const float* ln_u_scale = (const float*)d_in[9];
    const float* ln_u_bias  = (const float*)d_in[10];
    const float* W1_u       = (const float*)d_in[11];
    const float* b1_u       = (const float*)d_in[12];
    const float* W2_u       = (const float*)d_in[13];
    const float* b2_u       = (const float*)d_in[14];
    float* out = (float*)d_out;

    __half *a0, *h1, *gg, *h2;
    __half *w1dh, *w1dl, *w2dh, *w2dl, *w1uh, *w1ul, *w2uh, *w2ul;
    cudaGetSymbolAddress((void**)&a0, g_A0);
    cudaGetSymbolAddress((void**)&h1, g_H1);
    cudaGetSymbolAddress((void**)&gg, g_G);
    cudaGetSymbolAddress((void**)&h2, g_H2);
    cudaGetSymbolAddress((void**)&w1dh, g_w1dh); cudaGetSymbolAddress((void**)&w1dl, g_w1dl);
    cudaGetSymbolAddress((void**)&w2dh, g_w2dh); cudaGetSymbolAddress((void**)&w2dl, g_w2dl);
    cudaGetSymbolAddress((void**)&w1uh, g_w1uh); cudaGetSymbolAddress((void**)&w1ul, g_w1ul);
    cudaGetSymbolAddress((void**)&w2uh, g_w2uh); cudaGetSymbolAddress((void**)&w2ul, g_w2ul);

    const int DYN = 3 * STG_BYTES;   // 82944
    cudaFuncSetAttribute(mma_gemm<1>, cudaFuncAttributeMaxDynamicSharedMemorySize, DYN);
    cudaFuncSetAttribute(mma_gemm<2>, cudaFuncAttributeMaxDynamicSharedMemorySize, DYN);
    cudaFuncSetAttribute(mma_gemm<3>, cudaFuncAttributeMaxDynamicSharedMemorySize, DYN);

    // weight prep: one launch for all four weights
    k_wsplit_all<<<288, dim3(32, 8)>>>(W1_d, W2_d, W1_u, W2_u);

    // front-end (duplicate-aware)
    const int FB = (ROWS + 7) / 8;
    k_clr     <<<(T_STEPS * NUM_NODES + 255) / 256, 256>>>();
    k_count   <<<(ROWS + 255) / 256, 256>>>(indices);
    k_zero_dup<<<FB, 256>>>(indices);
    k_scat_dup<<<FB, 256>>>(x, indices);
    k_gather_ln<<<FB, 256>>>(x, batched_x, indices, ln_d_scale, ln_d_bias);

    // GEMM chain (fp16, split-B, 2 streams, 64x128 blocks)
    mma_gemm<1><<<dim3(H_DIM / 128, MBLK64), 256, DYN>>>(a0, w1dh, w1dl, b1_d,
                                                         nullptr, nullptr,
                                                         h1, nullptr, ROWS, H_DIM, E_DIM);
    mma_gemm<3><<<dim3(1, MBLK64), 256, DYN>>>(h1, w2dh, w2dl, b2_d,
                                               ln_u_scale, ln_u_bias,
                                               gg, nullptr, ROWS, C_DIM, H_DIM);
    mma_gemm<1><<<dim3(U_DIM / 128, MBLK64), 256, DYN>>>(gg, w1uh, w1ul, b1_u,
                                                         nullptr, nullptr,
                                                         h2, nullptr, ROWS, U_DIM, C_DIM);
    mma_gemm<2><<<dim3(E_DIM / 128, MBLK64), 256, DYN>>>(h2, w2uh, w2ul, b2_u,
                                                         nullptr, nullptr,
                                                         nullptr, out, ROWS, E_DIM, U_DIM);
}

// round 13
// speedup vs baseline: 1.4961x; 1.4961x over previous
#include <cuda_runtime.h>
#include <cuda_fp16.h>
#include <math.h>
#include <stdint.h>

// ---------------- problem dims (fixed) ----------------
#define T_STEPS   4
#define NODE_NUM  10000
#define NUM_NODES 50000
#define E_DIM     256
#define H_DIM     512
#define C_DIM     128
#define U_DIM     256
#define ROWS      (T_STEPS * NODE_NUM)   // 40000
#define LN_EPS    1e-5f
#define MBLK64    (ROWS / 64)            // 625 (exact)

// ---------------- scratch (__device__ globals) ----------------
__device__ float g_S[(size_t)T_STEPS * NUM_NODES * E_DIM];
__device__ int   g_cnt[T_STEPS * NUM_NODES];
__device__ int   g_tick[ROWS];
__device__ __half g_A0[(size_t)ROWS * E_DIM];
__device__ __half g_H1[(size_t)ROWS * H_DIM];
__device__ __half g_G [(size_t)ROWS * C_DIM];
__device__ __half g_H2[(size_t)ROWS * U_DIM];
// transposed fp16 weights, [N][K]
__device__ __half g_w1d[H_DIM * E_DIM];
__device__ __half g_w2d[C_DIM * H_DIM];
__device__ __half g_w1u[U_DIM * C_DIM];
__device__ __half g_w2u[E_DIM * U_DIM];

// ---------------- helpers ----------------
static __device__ __forceinline__ uint32_t smem_u32(const void* p) {
    uint32_t a;
    asm("{ .reg .u64 t; cvta.to.shared.u64 t, %1; cvt.u32.u64 %0, t; }" : "=r"(a) : "l"(p));
    return a;
}

static __device__ __forceinline__ float gelu_exact(float v) {
    return 0.5f * v * (1.0f + erff(v * 0.70710678118654752f));
}

#define CP_ASYNC16_U(dst, src) \
    asm volatile("cp.async.cg.shared.global [%0], [%1], 16;" \
                 :: "r"(dst), "l"(src) : "memory")
#define CP_COMMIT() asm volatile("cp.async.commit_group;" ::: "memory")
#define CP_WAIT1()  asm volatile("cp.async.wait_group 1;" ::: "memory")

#define LDMATRIX_X4(r0, r1, r2, r3, addr) \
    asm volatile("ldmatrix.sync.aligned.m8n8.x4.shared.b16 {%0,%1,%2,%3}, [%4];" \
                 : "=r"(r0), "=r"(r1), "=r"(r2), "=r"(r3) : "r"(addr))

#define MMA16816(c0, c1, c2, c3, a0, a1, a2, a3, b0, b1) \
    asm volatile("mma.sync.aligned.m16n8k16.row.col.f32.f16.f16.f32 " \
                 "{%0,%1,%2,%3}, {%4,%5,%6,%7}, {%8,%9}, {%0,%1,%2,%3};" \
                 : "+f"(c0), "+f"(c1), "+f"(c2), "+f"(c3) \
                 : "r"(a0), "r"(a1), "r"(a2), "r"(a3), "r"(b0), "r"(b1))

// ---------------- prep: ALL four weights in one launch ----------------
// Each 32x32 tile: coalesced transpose + fp16 quantize. 288 blocks total.
__global__ void k_wsplit_all(const float* __restrict__ W1d, const float* __restrict__ W2d,
                             const float* __restrict__ W1u, const float* __restrict__ W2u) {
    __shared__ float tile[32][33];
    int b = blockIdx.x;
    const float* W; __half *hi; int K, N, nb, kb;
    if (b < 128) {          // W1d: K=256, N=512 -> grid 16 x 8
        W = W1d; hi = g_w1d; K = E_DIM; N = H_DIM;
        nb = (b & 15) * 32; kb = (b >> 4) * 32;
    } else if (b < 192) {   // W2d: K=512, N=128 -> grid 4 x 16
        b -= 128; W = W2d; hi = g_w2d; K = H_DIM; N = C_DIM;
        nb = (b & 3) * 32; kb = (b >> 2) * 32;
    } else if (b < 224) {   // W1u: K=128, N=256 -> grid 8 x 4
        b -= 192; W = W1u; hi = g_w1u; K = C_DIM; N = U_DIM;
        nb = (b & 7) * 32; kb = (b >> 3) * 32;
    } else {                // W2u: K=256, N=256 -> grid 8 x 8
        b -= 224; W = W2u; hi = g_w2u; K = U_DIM; N = E_DIM;
        nb = (b & 7) * 32; kb = (b >> 3) * 32;
    }
    int tx = threadIdx.x, ty = threadIdx.y;
    #pragma unroll
    for (int i = 0; i < 32; i += 8)
        tile[ty + i][tx] = W[(size_t)(kb + ty + i) * N + nb + tx];
    __syncthreads();
    #pragma unroll
    for (int i = 0; i < 32; i += 8) {
        int n = nb + ty + i, k = kb + tx;
        hi[(size_t)n * K + k] = __float2half_rn(tile[tx][ty + i]);
    }
}

// ---------------- front-end (duplicate-aware) ----------------
__global__ void k_clr() {
    int i = blockIdx.x * 256 + threadIdx.x;
    if (i < T_STEPS * NUM_NODES) g_cnt[i] = 0;
}

__global__ void k_count(const int* __restrict__ idx) {
    int r = blockIdx.x * 256 + threadIdx.x;
    if (r >= ROWS) return;
    int t = r / NODE_NUM;
    g_tick[r] = atomicAdd(&g_cnt[t * NUM_NODES + idx[r]], 1);
}

__global__ void k_zero_dup(const int* __restrict__ idx) {
    int r = blockIdx.x * 8 + (threadIdx.x >> 5);
    if (r >= ROWS) return;
    int t = r / NODE_NUM;
    int node = idx[r];
    if (g_cnt[t * NUM_NODES + node] < 2 || g_tick[r] != 0) return;
    int lane = threadIdx.x & 31;
    float4* p = (float4*)&g_S[((size_t)t * NUM_NODES + node) * E_DIM];
    float4 z = make_float4(0.f, 0.f, 0.f, 0.f);
    p[lane] = z; p[lane + 32] = z;
}

__global__ void k_scat_dup(const float* __restrict__ x, const int* __restrict__ idx) {
    int r = blockIdx.x * 8 + (threadIdx.x >> 5);
    if (r >= ROWS) return;
    int t = r / NODE_NUM;
    int node = idx[r];
    if (g_cnt[t * NUM_NODES + node] < 2) return;
    int lane = threadIdx.x & 31;
    float* dst = &g_S[((size_t)t * NUM_NODES + node) * E_DIM];
    const float* src = x + (size_t)r * E_DIM;
    #pragma unroll
    for (int j = 0; j < 8; j++)
        atomicAdd(dst + lane + j * 32, src[lane + j * 32]);
}

// gather + broadcast-add + LN(256) -> fp16 A0
__global__ void k_gather_ln(const float* __restrict__ x, const float* __restrict__ bx,
                            const int* __restrict__ idx,
                            const float* __restrict__ sc, const float* __restrict__ bi) {
    int r = blockIdx.x * 8 + (threadIdx.x >> 5);
    if (r >= ROWS) return;
    int lane = threadIdx.x & 31;
    int t = r / NODE_NUM;
    int node = idx[r];
    const float* srow = (g_cnt[t * NUM_NODES + node] < 2)
                      ? (x + (size_t)r * E_DIM)
                      : &g_S[((size_t)t * NUM_NODES + node) * E_DIM];
    const float* brow = bx + (size_t)node * E_DIM;
    float4 a0 = *(const float4*)(srow + lane * 4);
    float4 a1 = *(const float4*)(srow + 128 + lane * 4);
    float4 b0 = *(const float4*)(brow + lane * 4);
    float4 b1 = *(const float4*)(brow + 128 + lane * 4);
    float v[8] = { a0.x + b0.x, a0.y + b0.y, a0.z + b0.z, a0.w + b0.w,
                   a1.x + b1.x, a1.y + b1.y, a1.z + b1.z, a1.w + b1.w };
    float s1 = 0.f, s2 = 0.f;
    #pragma unroll
    for (int j = 0; j < 8; j++) { s1 += v[j]; s2 += v[j] * v[j]; }
    #pragma unroll
    for (int o = 16; o > 0; o >>= 1) {
        s1 += __shfl_xor_sync(0xffffffffu, s1, o);
        s2 += __shfl_xor_sync(0xffffffffu, s2, o);
    }
    float mu = s1 * (1.f / 256.f);
    float rs = rsqrtf(s2 * (1.f / 256.f) - mu * mu + LN_EPS);
    #pragma unroll
    for (int half_i = 0; half_i < 2; half_i++) {
        #pragma unroll
        for (int j = 0; j < 2; j++) {
            int c = half_i * 128 + lane * 4 + j * 2;
            float o0 = (v[half_i * 4 + j * 2 + 0] - mu) * rs * sc[c]     + bi[c];
            float o1 = (v[half_i * 4 + j * 2 + 1] - mu) * rs * sc[c + 1] + bi[c + 1];
            *(__half2*)&g_A0[(size_t)r * E_DIM + c] = __floats2half2_rn(o0, o1);
        }
    }
}

// ---------------- mma.sync fp16 GEMM (single-pass), block 64x128 ----------------
// 8 warps (2m x 4n), warp tile 32x32. M multiple of 64 (40000 = 625*64).
// EPI: 1 = bias+GELU -> fp16; 2 = bias -> fp32; 3 = bias+LN -> fp16 (N==128)
#define ROWB 144                    // padded smem row stride (bytes)
#define A_BYTES (64 * ROWB)         // 9216
#define STG_BYTES (192 * ROWB)      // A(64) + B(128) rows = 27648
#define LNPAD 132

template<int EPI>
__global__ void __launch_bounds__(256, 2) mma_gemm(
    const __half* __restrict__ A,
    const __half* __restrict__ B,
    const float* __restrict__ bias,
    const float* __restrict__ lns, const float* __restrict__ lnb,
    __half* __restrict__ Ch, float* __restrict__ Cf,
    int M, int N, int K)
{
    extern __shared__ char smem[];
    const uint32_t sbase = smem_u32(smem);
    const int t = threadIdx.x, wid = t >> 5, lane = t & 31;
    const int wm = wid >> 2, wn = wid & 3;       // 2 x 4 warps
    const int g = lane >> 2, tig = lane & 3;
    const int quad = lane >> 3, qr = lane & 7;
    const int bm = blockIdx.y * 64, bn = blockIdx.x * 128;
    const int nst = K >> 6;                      // single stream

    const int lrow = t >> 3, lc = t & 7;

    auto load_stage = [&](int st) {
        int s = st % 3;
        int kk = st << 6;
        const __half* As = A + kk;
        const __half* Bs = B + kk;
        uint32_t Ab = sbase + s * STG_BYTES;
        uint32_t Bb = Ab + A_BYTES;
        #pragma unroll
        for (int i = 0; i < 2; i++) {           // A: 64 rows
            int row = i * 32 + lrow;
            const __half* src = As + (size_t)(bm + row) * K + lc * 8;
            CP_ASYNC16_U(Ab + row * ROWB + lc * 16, src);
        }
        #pragma unroll
        for (int i = 0; i < 4; i++) {           // B: 128 rows
            int row = i * 32 + lrow;
            const __half* src = Bs + (size_t)(bn + row) * K + lc * 8;
            CP_ASYNC16_U(Bb + row * ROWB + lc * 16, src);
        }
    };

    float acc[2][4][4];
    #pragma unroll
    for (int a = 0; a < 2; a++)
        #pragma unroll
        for (int b = 0; b < 4; b++)
            #pragma unroll
            for (int c = 0; c < 4; c++) acc[a][b][c] = 0.f;

    load_stage(0); CP_COMMIT();
    if (nst > 1) load_stage(1);
    CP_COMMIT();

    for (int st = 0; st < nst; ++st) {
        CP_WAIT1();
        __syncthreads();
        if (st + 2 < nst) load_stage(st + 2);
        CP_COMMIT();
        int s = st % 3;
        uint32_t Ab = sbase + s * STG_BYTES;
        uint32_t Bb = Ab + A_BYTES;
        #pragma unroll
        for (int ks = 0; ks < 4; ks++) {
            int ch = ks * 2 + (quad >> 1);
            uint32_t a[2][4], b[2][4];
            #pragma unroll
            for (int mt = 0; mt < 2; mt++) {
                uint32_t ad = Ab + (uint32_t)(wm * 32 + mt * 16 + (quad & 1) * 8 + qr) * ROWB + ch * 16;
                LDMATRIX_X4(a[mt][0], a[mt][1], a[mt][2], a[mt][3], ad);
            }
            #pragma unroll
            for (int np = 0; np < 2; np++) {
                uint32_t ad = Bb + (uint32_t)(wn * 32 + np * 16 + (quad & 1) * 8 + qr) * ROWB + ch * 16;
                LDMATRIX_X4(b[np][0], b[np][1], b[np][2], b[np][3], ad);
            }
            #pragma unroll
            for (int mt = 0; mt < 2; mt++)
                #pragma unroll
                for (int nt = 0; nt < 4; nt++)
                    MMA16816(acc[mt][nt][0], acc[mt][nt][1], acc[mt][nt][2], acc[mt][nt][3],
                             a[mt][0], a[mt][1], a[mt][2], a[mt][3],
                             b[nt >> 1][nt & 1], b[nt >> 1][2 + (nt & 1)]);
        }
    }

    if (EPI == 3) {
        // ---- fused bias + LayerNorm(128) -> fp16 out (64 rows) ----
        float* sf = (float*)smem;   // [64][LNPAD]
        __syncthreads();
        #pragma unroll
        for (int mt = 0; mt < 2; mt++) {
            int lr0 = wm * 32 + mt * 16 + g;
            #pragma unroll
            for (int nt = 0; nt < 4; nt++) {
                int col = wn * 32 + nt * 8 + tig * 2;
                float bz0 = bias[col], bz1 = bias[col + 1];
                sf[lr0 * LNPAD + col]           = acc[mt][nt][0] + bz0;
                sf[lr0 * LNPAD + col + 1]       = acc[mt][nt][1] + bz1;
                sf[(lr0 + 8) * LNPAD + col]     = acc[mt][nt][2] + bz0;
                sf[(lr0 + 8) * LNPAD + col + 1] = acc[mt][nt][3] + bz1;
            }
        }
        __syncthreads();
        #pragma unroll
        for (int rr = 0; rr < 8; rr++) {
            int lr = wid * 8 + rr;
            int grow = bm + lr;
            float v[4];
            #pragma unroll
            for (int j = 0; j < 4; j++) v[j] = sf[lr * LNPAD + lane * 4 + j];
            float s1 = v[0] + v[1] + v[2] + v[3];
            float s2 = v[0]*v[0] + v[1]*v[1] + v[2]*v[2] + v[3]*v[3];
            #pragma unroll
            for (int o = 16; o > 0; o >>= 1) {
                s1 += __shfl_xor_sync(0xffffffffu, s1, o);
                s2 += __shfl_xor_sync(0xffffffffu, s2, o);
            }
            float mu = s1 * (1.f / 128.f);
            float rs = rsqrtf(s2 * (1.f / 128.f) - mu * mu + LN_EPS);
            #pragma unroll
            for (int j = 0; j < 2; j++) {
                int c = lane * 4 + j * 2;
                float o0 = (v[j * 2 + 0] - mu) * rs * lns[c]     + lnb[c];
                float o1 = (v[j * 2 + 1] - mu) * rs * lns[c + 1] + lnb[c + 1];
                *(__half2*)&Ch[(size_t)grow * C_DIM + c] = __floats2half2_rn(o0, o1);
            }
        }
    } else {
        #pragma unroll
        for (int mt = 0; mt < 2; mt++) {
            int r0 = bm + wm * 32 + mt * 16 + g;
            int r1 = r0 + 8;
            #pragma unroll
            for (int nt = 0; nt < 4; nt++) {
                int col = bn + wn * 32 + nt * 8 + tig * 2;
                float bz0 = bias[col], bz1 = bias[col + 1];
                float v0 = acc[mt][nt][0] + bz0, v1 = acc[mt][nt][1] + bz1;
                float v2 = acc[mt][nt][2] + bz0, v3 = acc[mt][nt][3] + bz1;
                if (EPI == 1) {
                    v0 = gelu_exact(v0); v1 = gelu_exact(v1);
                    v2 = gelu_exact(v2); v3 = gelu_exact(v3);
                }
                if (EPI == 2) {
                    *(float2*)&Cf[(size_t)r0 * N + col] = make_float2(v0, v1);
                    *(float2*)&Cf[(size_t)r1 * N + col] = make_float2(v2, v3);
                } else {
                    *(__half2*)&Ch[(size_t)r0 * N + col] = __floats2half2_rn(v0, v1);
                    *(__half2*)&Ch[(size_t)r1 * N + col] = __floats2half2_rn(v2, v3);
                }
            }
        }
    }
}

// ---------------- launcher ----------------
extern "C" void kernel_launch(void* const* d_in, const int* in_sizes, int n_in,
                              void* d_out, int out_size) {
    (void)in_sizes; (void)n_in; (void)out_size;
    const float* x          = (const float*)d_in[0];
    const float* batched_x  = (const float*)d_in[1];
    const int*   indices    = (const int*)  d_in[2];
    const float* ln_d_scale = (const float*)d_in[3];
    const float* ln_d_bias  = (const float*)d_in[4];
    const float* W1_d       = (const float*)d_in[5];
    const float* b1_d       = (const float*)d_in[6];
    const float* W2_d       = (const float*)d_in[7];
    const float* b2_d       = (const float*)d_in[8];
    const float* ln_u_scale = (const float*)d_in[9];
    const float* ln_u_bias  = (const float*)d_in[10];
    const float* W1_u       = (const float*)d_in[11];
    const float* b1_u       = (const float*)d_in[12];
    const float* W2_u       = (const float*)d_in[13];
    const float* b2_u       = (const float*)d_in[14];
    float* out = (float*)d_out;

    __half *a0, *h1, *gg, *h2, *w1d, *w2d, *w1u, *w2u;
    cudaGetSymbolAddress((void**)&a0, g_A0);
    cudaGetSymbolAddress((void**)&h1, g_H1);
    cudaGetSymbolAddress((void**)&gg, g_G);
    cudaGetSymbolAddress((void**)&h2, g_H2);
    cudaGetSymbolAddress((void**)&w1d, g_w1d);
    cudaGetSymbolAddress((void**)&w2d, g_w2d);
    cudaGetSymbolAddress((void**)&w1u, g_w1u);
    cudaGetSymbolAddress((void**)&w2u, g_w2u);

    const int DYN = 3 * STG_BYTES;   // 82944
    cudaFuncSetAttribute(mma_gemm<1>, cudaFuncAttributeMaxDynamicSharedMemorySize, DYN);
    cudaFuncSetAttribute(mma_gemm<2>, cudaFuncAttributeMaxDynamicSharedMemorySize, DYN);
    cudaFuncSetAttribute(mma_gemm<3>, cudaFuncAttributeMaxDynamicSharedMemorySize, DYN);

    // weight prep: one launch for all four weights
    k_wsplit_all<<<288, dim3(32, 8)>>>(W1_d, W2_d, W1_u, W2_u);

    // front-end (duplicate-aware)
    const int FB = (ROWS + 7) / 8;
    k_clr     <<<(T_STEPS * NUM_NODES + 255) / 256, 256>>>();
    k_count   <<<(ROWS + 255) / 256, 256>>>(indices);
    k_zero_dup<<<FB, 256>>>(indices);
    k_scat_dup<<<FB, 256>>>(x, indices);
    k_gather_ln<<<FB, 256>>>(x, batched_x, indices, ln_d_scale, ln_d_bias);

    // GEMM chain (fp16 single-pass, 64x128 blocks)
    mma_gemm<1><<<dim3(H_DIM / 128, MBLK64), 256, DYN>>>(a0, w1d, b1_d,
                                                         nullptr, nullptr,
                                                         h1, nullptr, ROWS, H_DIM, E_DIM);
    mma_gemm<3><<<dim3(1, MBLK64), 256, DYN>>>(h1, w2d, b2_d,
                                               ln_u_scale, ln_u_bias,
                                               gg, nullptr, ROWS, C_DIM, H_DIM);
    mma_gemm<1><<<dim3(U_DIM / 128, MBLK64), 256, DYN>>>(gg, w1u, b1_u,
                                                         nullptr, nullptr,
                                                         h2, nullptr, ROWS, U_DIM, C_DIM);
    mma_gemm<2><<<dim3(E_DIM / 128, MBLK64), 256, DYN>>>(h2, w2u, b2_u,
                                                         nullptr, nullptr,
                                                         nullptr, out, ROWS, E_DIM, U_DIM);
}

// round 16
// speedup vs baseline: 1.5518x; 1.0372x over previous
#include <cuda_runtime.h>
#include <cuda_fp16.h>
#include <math.h>
#include <stdint.h>

// ---------------- problem dims (fixed) ----------------
#define T_STEPS   4
#define NODE_NUM  10000
#define NUM_NODES 50000
#define E_DIM     256
#define H_DIM     512
#define C_DIM     128
#define U_DIM     256
#define ROWS      (T_STEPS * NODE_NUM)   // 40000
#define LN_EPS    1e-5f
#define MBLK64    (ROWS / 64)            // 625 (exact)
#define NKEYS     (T_STEPS * NUM_NODES)  // 200000

// ---------------- scratch (__device__ globals) ----------------
__device__ int   g_head[NKEYS];
__device__ int   g_link[ROWS];
__device__ __half g_A0[(size_t)ROWS * E_DIM];
__device__ __half g_H1[(size_t)ROWS * H_DIM];
__device__ __half g_G [(size_t)ROWS * C_DIM];
__device__ __half g_H2[(size_t)ROWS * U_DIM];
// transposed fp16 weights, [N][K]
__device__ __half g_w1d[H_DIM * E_DIM];
__device__ __half g_w2d[C_DIM * H_DIM];
__device__ __half g_w1u[U_DIM * C_DIM];
__device__ __half g_w2u[E_DIM * U_DIM];

// ---------------- helpers ----------------
static __device__ __forceinline__ uint32_t smem_u32(const void* p) {
    uint32_t a;
    asm("{ .reg .u64 t; cvta.to.shared.u64 t, %1; cvt.u32.u64 %0, t; }" : "=r"(a) : "l"(p));
    return a;
}

static __device__ __forceinline__ float gelu_exact(float v) {
    return 0.5f * v * (1.0f + erff(v * 0.70710678118654752f));
}

#define CP_ASYNC16_U(dst, src) \
    asm volatile("cp.async.cg.shared.global [%0], [%1], 16;" \
                 :: "r"(dst), "l"(src) : "memory")
#define CP_COMMIT() asm volatile("cp.async.commit_group;" ::: "memory")
#define CP_WAIT1()  asm volatile("cp.async.wait_group 1;" ::: "memory")

#define LDMATRIX_X4(r0, r1, r2, r3, addr) \
    asm volatile("ldmatrix.sync.aligned.m8n8.x4.shared.b16 {%0,%1,%2,%3}, [%4];" \
                 : "=r"(r0), "=r"(r1), "=r"(r2), "=r"(r3) : "r"(addr))

#define MMA16816(c0, c1, c2, c3, a0, a1, a2, a3, b0, b1) \
    asm volatile("mma.sync.aligned.m16n8k16.row.col.f32.f16.f16.f32 " \
                 "{%0,%1,%2,%3}, {%4,%5,%6,%7}, {%8,%9}, {%0,%1,%2,%3};" \
                 : "+f"(c0), "+f"(c1), "+f"(c2), "+f"(c3) \
                 : "r"(a0), "r"(a1), "r"(a2), "r"(a3), "r"(b0), "r"(b1))

// ---------------- prep: weights transpose+fp16 AND head-clear in ONE launch ----
// blocks [0,288): weight tiles; blocks [288, 288+196): clear g_head to -1.
#define CLR_BLKS 196
__global__ void k_prep_all(const float* __restrict__ W1d, const float* __restrict__ W2d,
                           const float* __restrict__ W1u, const float* __restrict__ W2u) {
    int b = blockIdx.x;
    int tid = threadIdx.y * 32 + threadIdx.x;
    if (b >= 288) {                   // head-clear region
        int base = (b - 288) * 1024;
        #pragma unroll
        for (int j = 0; j < 4; j++) {
            int i = base + j * 256 + tid;
            if (i < NKEYS) g_head[i] = -1;
        }
        return;
    }
    __shared__ float tile[32][33];
    const float* W; __half *hi; int K, N, nb, kb;
    if (b < 128) {          // W1d: K=256, N=512 -> grid 16 x 8
        W = W1d; hi = g_w1d; K = E_DIM; N = H_DIM;
        nb = (b & 15) * 32; kb = (b >> 4) * 32;
    } else if (b < 192) {   // W2d: K=512, N=128 -> grid 4 x 16
        b -= 128; W = W2d; hi = g_w2d; K = H_DIM; N = C_DIM;
        nb = (b & 3) * 32; kb = (b >> 2) * 32;
    } else if (b < 224) {   // W1u: K=128, N=256 -> grid 8 x 4
        b -= 192; W = W1u; hi = g_w1u; K = C_DIM; N = U_DIM;
        nb = (b & 7) * 32; kb = (b >> 3) * 32;
    } else {                // W2u: K=256, N=256 -> grid 8 x 8
        b -= 224; W = W2u; hi = g_w2u; K = U_DIM; N = E_DIM;
        nb = (b & 7) * 32; kb = (b >> 3) * 32;
    }
    int tx = threadIdx.x, ty = threadIdx.y;
    #pragma unroll
    for (int i = 0; i < 32; i += 8)
        tile[ty + i][tx] = W[(size_t)(kb + ty + i) * N + nb + tx];
    __syncthreads();
    #pragma unroll
    for (int i = 0; i < 32; i += 8) {
        int n = nb + ty + i, k = kb + tx;
        hi[(size_t)n * K + k] = __float2half_rn(tile[tx][ty + i]);
    }
}

// ---------------- link: per-(t,node) chains via atomicExch ----------------
__global__ void k_link(const int* __restrict__ idx) {
    int r = blockIdx.x * 256 + threadIdx.x;
    if (r >= ROWS) return;
    int t = r / NODE_NUM;
    g_link[r] = atomicExch(&g_head[t * NUM_NODES + idx[r]], r);
}

// ---------------- gather: chain-head sums x rows + bx, LN(256), writes all ----
__global__ void k_gather_ln(const float* __restrict__ x, const float* __restrict__ bx,
                            const int* __restrict__ idx,
                            const float* __restrict__ sc, const float* __restrict__ bi) {
    int r = blockIdx.x * 8 + (threadIdx.x >> 5);
    if (r >= ROWS) return;
    int lane = threadIdx.x & 31;
    int t = r / NODE_NUM;
    int node = idx[r];
    int key = t * NUM_NODES + node;
    if (g_head[key] != r) return;     // only the chain head works

    // walk chain, summing x rows (chain covers every row with this key)
    float v[8] = {0.f, 0.f, 0.f, 0.f, 0.f, 0.f, 0.f, 0.f};
    int cur = r;
    while (cur >= 0) {
        const float* xr = x + (size_t)cur * E_DIM;
        float4 a0 = *(const float4*)(xr + lane * 4);
        float4 a1 = *(const float4*)(xr + 128 + lane * 4);
        v[0] += a0.x; v[1] += a0.y; v[2] += a0.z; v[3] += a0.w;
        v[4] += a1.x; v[5] += a1.y; v[6] += a1.z; v[7] += a1.w;
        int nxt;
        if (lane == 0) nxt = g_link[cur];
        cur = __shfl_sync(0xffffffffu, nxt, 0);
    }
    // broadcast entire-feature add
    const float* brow = bx + (size_t)node * E_DIM;
    float4 b0 = *(const float4*)(brow + lane * 4);
    float4 b1 = *(const float4*)(brow + 128 + lane * 4);
    v[0] += b0.x; v[1] += b0.y; v[2] += b0.z; v[3] += b0.w;
    v[4] += b1.x; v[5] += b1.y; v[6] += b1.z; v[7] += b1.w;

    float s1 = 0.f, s2 = 0.f;
    #pragma unroll
    for (int j = 0; j < 8; j++) { s1 += v[j]; s2 += v[j] * v[j]; }
    #pragma unroll
    for (int o = 16; o > 0; o >>= 1) {
        s1 += __shfl_xor_sync(0xffffffffu, s1, o);
        s2 += __shfl_xor_sync(0xffffffffu, s2, o);
    }
    float mu = s1 * (1.f / 256.f);
    float rs = rsqrtf(s2 * (1.f / 256.f) - mu * mu + LN_EPS);

    __half2 o[8];
    #pragma unroll
    for (int half_i = 0; half_i < 2; half_i++) {
        #pragma unroll
        for (int j = 0; j < 2; j++) {
            int c = half_i * 128 + lane * 4 + j * 2;
            float o0 = (v[half_i * 4 + j * 2 + 0] - mu) * rs * sc[c]     + bi[c];
            float o1 = (v[half_i * 4 + j * 2 + 1] - mu) * rs * sc[c + 1] + bi[c + 1];
            o[half_i * 2 + j] = __floats2half2_rn(o0, o1);
        }
    }
    // write identical LN row to every chain member
    cur = r;
    while (cur >= 0) {
        __half* orow = &g_A0[(size_t)cur * E_DIM];
        *(__half2*)(orow + lane * 4)           = o[0];
        *(__half2*)(orow + lane * 4 + 2)       = o[1];
        *(__half2*)(orow + 128 + lane * 4)     = o[2];
        *(__half2*)(orow + 128 + lane * 4 + 2) = o[3];
        int nxt;
        if (lane == 0) nxt = g_link[cur];
        cur = __shfl_sync(0xffffffffu, nxt, 0);
    }
}

// ---------------- mma.sync fp16 GEMM (single-pass), block 64x128 ----------------
// 8 warps (2m x 4n), warp tile 32x32. M multiple of 64 (40000 = 625*64).
// EPI: 1 = bias+GELU -> fp16; 2 = bias -> fp32; 3 = bias+LN -> fp16 (N==128)
#define ROWB 144                    // padded smem row stride (bytes)
#define A_BYTES (64 * ROWB)         // 9216
#define STG_BYTES (192 * ROWB)      // A(64) + B(128) rows = 27648
#define LNPAD 132

template<int EPI>
__global__ void __launch_bounds__(256, 2) mma_gemm(
    const __half* __restrict__ A,
    const __half* __restrict__ B,
    const float* __restrict__ bias,
    const float* __restrict__ lns, const float* __restrict__ lnb,
    __half* __restrict__ Ch, float* __restrict__ Cf,
    int M, int N, int K)
{
    extern __shared__ char smem[];
    const uint32_t sbase = smem_u32(smem);
    const int t = threadIdx.x, wid = t >> 5, lane = t & 31;
    const int wm = wid >> 2, wn = wid & 3;       // 2 x 4 warps
    const int g = lane >> 2, tig = lane & 3;
    const int quad = lane >> 3, qr = lane & 7;
    const int bm = blockIdx.y * 64, bn = blockIdx.x * 128;
    const int nst = K >> 6;                      // single stream

    const int lrow = t >> 3, lc = t & 7;

    auto load_stage = [&](int st) {
        int s = st % 3;
        int kk = st << 6;
        const __half* As = A + kk;
        const __half* Bs = B + kk;
        uint32_t Ab = sbase + s * STG_BYTES;
        uint32_t Bb = Ab + A_BYTES;
        #pragma unroll
        for (int i = 0; i < 2; i++) {           // A: 64 rows
            int row = i * 32 + lrow;
            const __half* src = As + (size_t)(bm + row) * K + lc * 8;
            CP_ASYNC16_U(Ab + row * ROWB + lc * 16, src);
        }
        #pragma unroll
        for (int i = 0; i < 4; i++) {           // B: 128 rows
            int row = i * 32 + lrow;
            const __half* src = Bs + (size_t)(bn + row) * K + lc * 8;
            CP_ASYNC16_U(Bb + row * ROWB + lc * 16, src);
        }
    };

    float acc[2][4][4];
    #pragma unroll
    for (int a = 0; a < 2; a++)
        #pragma unroll
        for (int b = 0; b < 4; b++)
            #pragma unroll
            for (int c = 0; c < 4; c++) acc[a][b][c] = 0.f;

    load_stage(0); CP_COMMIT();
    if (nst > 1) load_stage(1);
    CP_COMMIT();

    for (int st = 0; st < nst; ++st) {
        CP_WAIT1();
        __syncthreads();
        if (st + 2 < nst) load_stage(st + 2);
        CP_COMMIT();
        int s = st % 3;
        uint32_t Ab = sbase + s * STG_BYTES;
        uint32_t Bb = Ab + A_BYTES;
        #pragma unroll
        for (int ks = 0; ks < 4; ks++) {
            int ch = ks * 2 + (quad >> 1);
            uint32_t a[2][4], b[2][4];
            #pragma unroll
            for (int mt = 0; mt < 2; mt++) {
                uint32_t ad = Ab + (uint32_t)(wm * 32 + mt * 16 + (quad & 1) * 8 + qr) * ROWB + ch * 16;
                LDMATRIX_X4(a[mt][0], a[mt][1], a[mt][2], a[mt][3], ad);
            }
            #pragma unroll
            for (int np = 0; np < 2; np++) {
                uint32_t ad = Bb + (uint32_t)(wn * 32 + np * 16 + (quad & 1) * 8 + qr) * ROWB + ch * 16;
                LDMATRIX_X4(b[np][0], b[np][1], b[np][2], b[np][3], ad);
            }
            #pragma unroll
            for (int mt = 0; mt < 2; mt++)
                #pragma unroll
                for (int nt = 0; nt < 4; nt++)
                    MMA16816(acc[mt][nt][0], acc[mt][nt][1], acc[mt][nt][2], acc[mt][nt][3],
                             a[mt][0], a[mt][1], a[mt][2], a[mt][3],
                             b[nt >> 1][nt & 1], b[nt >> 1][2 + (nt & 1)]);
        }
    }

    if (EPI == 3) {
        // ---- fused bias + LayerNorm(128) -> fp16 out (64 rows) ----
        float* sf = (float*)smem;   // [64][LNPAD]
        __syncthreads();
        #pragma unroll
        for (int mt = 0; mt < 2; mt++) {
            int lr0 = wm * 32 + mt * 16 + g;
            #pragma unroll
            for (int nt = 0; nt < 4; nt++) {
                int col = wn * 32 + nt * 8 + tig * 2;
                float bz0 = bias[col], bz1 = bias[col + 1];
                sf[lr0 * LNPAD + col]           = acc[mt][nt][0] + bz0;
                sf[lr0 * LNPAD + col + 1]       = acc[mt][nt][1] + bz1;
                sf[(lr0 + 8) * LNPAD + col]     = acc[mt][nt][2] + bz0;
                sf[(lr0 + 8) * LNPAD + col + 1] = acc[mt][nt][3] + bz1;
            }
        }
        __syncthreads();
        #pragma unroll
        for (int rr = 0; rr < 8; rr++) {
            int lr = wid * 8 + rr;
            int grow = bm + lr;
            float v[4];
            #pragma unroll
            for (int j = 0; j < 4; j++) v[j] = sf[lr * LNPAD + lane * 4 + j];
            float s1 = v[0] + v[1] + v[2] + v[3];
            float s2 = v[0]*v[0] + v[1]*v[1] + v[2]*v[2] + v[3]*v[3];
            #pragma unroll
            for (int o = 16; o > 0; o >>= 1) {
                s1 += __shfl_xor_sync(0xffffffffu, s1, o);
                s2 += __shfl_xor_sync(0xffffffffu, s2, o);
            }
            float mu = s1 * (1.f / 128.f);
            float rs = rsqrtf(s2 * (1.f / 128.f) - mu * mu + LN_EPS);
            #pragma unroll
            for (int j = 0; j < 2; j++) {
                int c = lane * 4 + j * 2;
                float o0 = (v[j * 2 + 0] - mu) * rs * lns[c]     + lnb[c];
                float o1 = (v[j * 2 + 1] - mu) * rs * lns[c + 1] + lnb[c + 1];
                *(__half2*)&Ch[(size_t)grow * C_DIM + c] = __floats2half2_rn(o0, o1);
            }
        }
    } else {
        #pragma unroll
        for (int mt = 0; mt < 2; mt++) {
            int r0 = bm + wm * 32 + mt * 16 + g;
            int r1 = r0 + 8;
            #pragma unroll
            for (int nt = 0; nt < 4; nt++) {
                int col = bn + wn * 32 + nt * 8 + tig * 2;
                float bz0 = bias[col], bz1 = bias[col + 1];
                float v0 = acc[mt][nt][0] + bz0, v1 = acc[mt][nt][1] + bz1;
                float v2 = acc[mt][nt][2] + bz0, v3 = acc[mt][nt][3] + bz1;
                if (EPI == 1) {
                    v0 = gelu_exact(v0); v1 = gelu_exact(v1);
                    v2 = gelu_exact(v2); v3 = gelu_exact(v3);
                }
                if (EPI == 2) {
                    *(float2*)&Cf[(size_t)r0 * N + col] = make_float2(v0, v1);
                    *(float2*)&Cf[(size_t)r1 * N + col] = make_float2(v2, v3);
                } else {
                    *(__half2*)&Ch[(size_t)r0 * N + col] = __floats2half2_rn(v0, v1);
                    *(__half2*)&Ch[(size_t)r1 * N + col] = __floats2half2_rn(v2, v3);
                }
            }
        }
    }
}

// ---------------- launcher ----------------
extern "C" void kernel_launch(void* const* d_in, const int* in_sizes, int n_in,
                              void* d_out, int out_size) {
    (void)in_sizes; (void)n_in; (void)out_size;
    const float* x          = (const float*)d_in[0];
    const float* batched_x  = (const float*)d_in[1];
    const int*   indices    = (const int*)  d_in[2];
    const float* ln_d_scale = (const float*)d_in[3];
    const float* ln_d_bias  = (const float*)d_in[4];
    const float* W1_d       = (const float*)d_in[5];
    const float* b1_d       = (const float*)d_in[6];
    const float* W2_d       = (const float*)d_in[7];
    const float* b2_d       = (const float*)d_in[8];
    const float* ln_u_scale = (const float*)d_in[9];
    const float* ln_u_bias  = (const float*)d_in[10];
    const float* W1_u       = (const float*)d_in[11];
    const float* b1_u       = (const float*)d_in[12];
    const float* W2_u       = (const float*)d_in[13];
    const float* b2_u       = (const float*)d_in[14];
    float* out = (float*)d_out;

    __half *a0, *h1, *gg, *h2, *w1d, *w2d, *w1u, *w2u;
    cudaGetSymbolAddress((void**)&a0, g_A0);
    cudaGetSymbolAddress((void**)&h1, g_H1);
    cudaGetSymbolAddress((void**)&gg, g_G);
    cudaGetSymbolAddress((void**)&h2, g_H2);
    cudaGetSymbolAddress((void**)&w1d, g_w1d);
    cudaGetSymbolAddress((void**)&w2d, g_w2d);
    cudaGetSymbolAddress((void**)&w1u, g_w1u);
    cudaGetSymbolAddress((void**)&w2u, g_w2u);

    const int DYN = 3 * STG_BYTES;   // 82944
    cudaFuncSetAttribute(mma_gemm<1>, cudaFuncAttributeMaxDynamicSharedMemorySize, DYN);
    cudaFuncSetAttribute(mma_gemm<2>, cudaFuncAttributeMaxDynamicSharedMemorySize, DYN);
    cudaFuncSetAttribute(mma_gemm<3>, cudaFuncAttributeMaxDynamicSharedMemorySize, DYN);

    // 1) weights transpose+quantize AND head-clear, one launch
    k_prep_all<<<288 + CLR_BLKS, dim3(32, 8)>>>(W1_d, W2_d, W1_u, W2_u);
    // 2) build dup chains
    k_link<<<(ROWS + 255) / 256, 256>>>(indices);
    // 3) gather + dedup-sum + broadcast-add + LN(256) -> fp16 A0
    k_gather_ln<<<(ROWS + 7) / 8, 256>>>(x, batched_x, indices, ln_d_scale, ln_d_bias);

    // GEMM chain (fp16 single-pass, 64x128 blocks)
    mma_gemm<1><<<dim3(H_DIM / 128, MBLK64), 256, DYN>>>(a0, w1d, b1_d,
                                                         nullptr, nullptr,
                                                         h1, nullptr, ROWS, H_DIM, E_DIM);
    mma_gemm<3><<<dim3(1, MBLK64), 256, DYN>>>(h1, w2d, b2_d,
                                               ln_u_scale, ln_u_bias,
                                               gg, nullptr, ROWS, C_DIM, H_DIM);
    mma_gemm<1><<<dim3(U_DIM / 128, MBLK64), 256, DYN>>>(gg, w1u, b1_u,
                                                         nullptr, nullptr,
                                                         h2, nullptr, ROWS, U_DIM, C_DIM);
    mma_gemm<2><<<dim3(E_DIM / 128, MBLK64), 256, DYN>>>(h2, w2u, b2_u,
                                                         nullptr, nullptr,
                                                         nullptr, out, ROWS, E_DIM, U_DIM);
}

// round 17
// speedup vs baseline: 1.5881x; 1.0234x over previous
#include <cuda_runtime.h>
#include <cuda_fp16.h>
#include <math.h>
#include <stdint.h>

// ---------------- problem dims (fixed) ----------------
#define T_STEPS   4
#define NODE_NUM  10000
#define NUM_NODES 50000
#define E_DIM     256
#define H_DIM     512
#define C_DIM     128
#define U_DIM     256
#define ROWS      (T_STEPS * NODE_NUM)   // 40000
#define LN_EPS    1e-5f
#define MBLK128   ((ROWS + 127) / 128)   // 313
#define NKEYS     (T_STEPS * NUM_NODES)  // 200000

// ---------------- scratch (__device__ globals) ----------------
__device__ int   g_head[NKEYS];
__device__ int   g_link[ROWS];
__device__ __half g_A0[(size_t)ROWS * E_DIM];
__device__ __half g_H1[(size_t)ROWS * H_DIM];
__device__ __half g_G [(size_t)ROWS * C_DIM];
__device__ __half g_H2[(size_t)ROWS * U_DIM];
// transposed fp16 weights, [N][K]
__device__ __half g_w1d[H_DIM * E_DIM];
__device__ __half g_w2d[C_DIM * H_DIM];
__device__ __half g_w1u[U_DIM * C_DIM];
__device__ __half g_w2u[E_DIM * U_DIM];

// ---------------- helpers ----------------
static __device__ __forceinline__ uint32_t smem_u32(const void* p) {
    uint32_t a;
    asm("{ .reg .u64 t; cvta.to.shared.u64 t, %1; cvt.u32.u64 %0, t; }" : "=r"(a) : "l"(p));
    return a;
}

static __device__ __forceinline__ float gelu_exact(float v) {
    return 0.5f * v * (1.0f + erff(v * 0.70710678118654752f));
}

#define CP_ASYNC16(dst, src, sz) \
    asm volatile("cp.async.cg.shared.global [%0], [%1], 16, %2;" \
                 :: "r"(dst), "l"(src), "r"(sz) : "memory")
#define CP_ASYNC16_U(dst, src) \
    asm volatile("cp.async.cg.shared.global [%0], [%1], 16;" \
                 :: "r"(dst), "l"(src) : "memory")
#define CP_COMMIT() asm volatile("cp.async.commit_group;" ::: "memory")
#define CP_WAIT1()  asm volatile("cp.async.wait_group 1;" ::: "memory")

#define LDMATRIX_X4(r0, r1, r2, r3, addr) \
    asm volatile("ldmatrix.sync.aligned.m8n8.x4.shared.b16 {%0,%1,%2,%3}, [%4];" \
                 : "=r"(r0), "=r"(r1), "=r"(r2), "=r"(r3) : "r"(addr))

#define MMA16816(c0, c1, c2, c3, a0, a1, a2, a3, b0, b1) \
    asm volatile("mma.sync.aligned.m16n8k16.row.col.f32.f16.f16.f32 " \
                 "{%0,%1,%2,%3}, {%4,%5,%6,%7}, {%8,%9}, {%0,%1,%2,%3};" \
                 : "+f"(c0), "+f"(c1), "+f"(c2), "+f"(c3) \
                 : "r"(a0), "r"(a1), "r"(a2), "r"(a3), "r"(b0), "r"(b1))

// ---------------- prep: weights transpose+fp16 AND head-clear in ONE launch ----
#define CLR_BLKS 196
__global__ void k_prep_all(const float* __restrict__ W1d, const float* __restrict__ W2d,
                           const float* __restrict__ W1u, const float* __restrict__ W2u) {
    int b = blockIdx.x;
    int tid = threadIdx.y * 32 + threadIdx.x;
    if (b >= 288) {                   // head-clear region
        int base = (b - 288) * 1024;
        #pragma unroll
        for (int j = 0; j < 4; j++) {
            int i = base + j * 256 + tid;
            if (i < NKEYS) g_head[i] = -1;
        }
        return;
    }
    __shared__ float tile[32][33];
    const float* W; __half *hi; int K, N, nb, kb;
    if (b < 128) {          // W1d: K=256, N=512 -> grid 16 x 8
        W = W1d; hi = g_w1d; K = E_DIM; N = H_DIM;
        nb = (b & 15) * 32; kb = (b >> 4) * 32;
    } else if (b < 192) {   // W2d: K=512, N=128 -> grid 4 x 16
        b -= 128; W = W2d; hi = g_w2d; K = H_DIM; N = C_DIM;
        nb = (b & 3) * 32; kb = (b >> 2) * 32;
    } else if (b < 224) {   // W1u: K=128, N=256 -> grid 8 x 4
        b -= 192; W = W1u; hi = g_w1u; K = C_DIM; N = U_DIM;
        nb = (b & 7) * 32; kb = (b >> 3) * 32;
    } else {                // W2u: K=256, N=256 -> grid 8 x 8
        b -= 224; W = W2u; hi = g_w2u; K = U_DIM; N = E_DIM;
        nb = (b & 7) * 32; kb = (b >> 3) * 32;
    }
    int tx = threadIdx.x, ty = threadIdx.y;
    #pragma unroll
    for (int i = 0; i < 32; i += 8)
        tile[ty + i][tx] = W[(size_t)(kb + ty + i) * N + nb + tx];
    __syncthreads();
    #pragma unroll
    for (int i = 0; i < 32; i += 8) {
        int n = nb + ty + i, k = kb + tx;
        hi[(size_t)n * K + k] = __float2half_rn(tile[tx][ty + i]);
    }
}

// ---------------- link: per-(t,node) chains via atomicExch ----------------
__global__ void k_link(const int* __restrict__ idx) {
    int r = blockIdx.x * 256 + threadIdx.x;
    if (r >= ROWS) return;
    int t = r / NODE_NUM;
    g_link[r] = atomicExch(&g_head[t * NUM_NODES + idx[r]], r);
}

// ---------------- gather: chain-head sums x rows + bx, LN(256), writes all ----
__global__ void k_gather_ln(const float* __restrict__ x, const float* __restrict__ bx,
                            const int* __restrict__ idx,
                            const float* __restrict__ sc, const float* __restrict__ bi) {
    int r = blockIdx.x * 8 + (threadIdx.x >> 5);
    if (r >= ROWS) return;
    int lane = threadIdx.x & 31;
    int t = r / NODE_NUM;
    int node = idx[r];
    int key = t * NUM_NODES + node;
    if (g_head[key] != r) return;     // only the chain head works

    float v[8] = {0.f, 0.f, 0.f, 0.f, 0.f, 0.f, 0.f, 0.f};
    int cur = r;
    while (cur >= 0) {
        const float* xr = x + (size_t)cur * E_DIM;
        float4 a0 = *(const float4*)(xr + lane * 4);
        float4 a1 = *(const float4*)(xr + 128 + lane * 4);
        v[0] += a0.x; v[1] += a0.y; v[2] += a0.z; v[3] += a0.w;
        v[4] += a1.x; v[5] += a1.y; v[6] += a1.z; v[7] += a1.w;
        int nxt;
        if (lane == 0) nxt = g_link[cur];
        cur = __shfl_sync(0xffffffffu, nxt, 0);
    }
    const float* brow = bx + (size_t)node * E_DIM;
    float4 b0 = *(const float4*)(brow + lane * 4);
    float4 b1 = *(const float4*)(brow + 128 + lane * 4);
    v[0] += b0.x; v[1] += b0.y; v[2] += b0.z; v[3] += b0.w;
    v[4] += b1.x; v[5] += b1.y; v[6] += b1.z; v[7] += b1.w;

    float s1 = 0.f, s2 = 0.f;
    #pragma unroll
    for (int j = 0; j < 8; j++) { s1 += v[j]; s2 += v[j] * v[j]; }
    #pragma unroll
    for (int o = 16; o > 0; o >>= 1) {
        s1 += __shfl_xor_sync(0xffffffffu, s1, o);
        s2 += __shfl_xor_sync(0xffffffffu, s2, o);
    }
    float mu = s1 * (1.f / 256.f);
    float rs = rsqrtf(s2 * (1.f / 256.f) - mu * mu + LN_EPS);

    __half2 o[4];
    #pragma unroll
    for (int half_i = 0; half_i < 2; half_i++) {
        #pragma unroll
        for (int j = 0; j < 2; j++) {
            int c = half_i * 128 + lane * 4 + j * 2;
            float o0 = (v[half_i * 4 + j * 2 + 0] - mu) * rs * sc[c]     + bi[c];
            float o1 = (v[half_i * 4 + j * 2 + 1] - mu) * rs * sc[c + 1] + bi[c + 1];
            o[half_i * 2 + j] = __floats2half2_rn(o0, o1);
        }
    }
    cur = r;
    while (cur >= 0) {
        __half* orow = &g_A0[(size_t)cur * E_DIM];
        *(__half2*)(orow + lane * 4)           = o[0];
        *(__half2*)(orow + lane * 4 + 2)       = o[1];
        *(__half2*)(orow + 128 + lane * 4)     = o[2];
        *(__half2*)(orow + 128 + lane * 4 + 2) = o[3];
        int nxt;
        if (lane == 0) nxt = g_link[cur];
        cur = __shfl_sync(0xffffffffu, nxt, 0);
    }
}

// ---------------- mma.sync fp16 GEMM (single-pass), block 128x128 ----------------
// 8 warps (2m x 4n), warp tile 64x32 -> 16 MMAs per ks chain. 3-stage pipeline, 2 CTA/SM.
// EPI: 1 = bias+GELU -> fp16; 2 = bias -> fp32; 3 = bias+LN -> fp16 (N==128)
#define ROWB 144                    // padded smem row stride (bytes)
#define STG_BYTES (256 * ROWB)      // A(128) + B(128) rows = 36864
#define LNPAD 132

template<int EPI>
__global__ void __launch_bounds__(256, 2) mma_gemm(
    const __half* __restrict__ A,
    const __half* __restrict__ B,
    const float* __restrict__ bias,
    const float* __restrict__ lns, const float* __restrict__ lnb,
    __half* __restrict__ Ch, float* __restrict__ Cf,
    int M, int N, int K)
{
    extern __shared__ char smem[];
    const uint32_t sbase = smem_u32(smem);
    const int t = threadIdx.x, wid = t >> 5, lane = t & 31;
    const int wm = wid >> 2, wn = wid & 3;       // 2 x 4 warps
    const int g = lane >> 2, tig = lane & 3;
    const int quad = lane >> 3, qr = lane & 7;
    const int bm = blockIdx.y * 128, bn = blockIdx.x * 128;
    const int nst = K >> 6;

    const int lrow = t >> 3, lc = t & 7;

    auto load_stage = [&](int st) {
        int s = st % 3;
        int kk = st << 6;
        const __half* As = A + kk;
        const __half* Bs = B + kk;
        uint32_t Ab = sbase + s * STG_BYTES;
        uint32_t Bb = Ab + 128 * ROWB;
        #pragma unroll
        for (int i = 0; i < 4; i++) {           // A: 128 rows (guarded)
            int row = i * 32 + lrow;
            int grow = bm + row;
            int sz = (grow < M) ? 16 : 0;
            const __half* src = As + (size_t)((grow < M) ? grow : (M - 1)) * K + lc * 8;
            CP_ASYNC16(Ab + row * ROWB + lc * 16, src, sz);
        }
        #pragma unroll
        for (int i = 0; i < 4; i++) {           // B: 128 rows
            int row = i * 32 + lrow;
            const __half* src = Bs + (size_t)(bn + row) * K + lc * 8;
            CP_ASYNC16_U(Bb + row * ROWB + lc * 16, src);
        }
    };

    float acc[4][4][4];
    #pragma unroll
    for (int a = 0; a < 4; a++)
        #pragma unroll
        for (int b = 0; b < 4; b++)
            #pragma unroll
            for (int c = 0; c < 4; c++) acc[a][b][c] = 0.f;

    load_stage(0); CP_COMMIT();
    if (nst > 1) load_stage(1);
    CP_COMMIT();

    for (int st = 0; st < nst; ++st) {
        CP_WAIT1();
        __syncthreads();
        if (st + 2 < nst) load_stage(st + 2);
        CP_COMMIT();
        int s = st % 3;
        uint32_t Ab = sbase + s * STG_BYTES;
        uint32_t Bb = Ab + 128 * ROWB;
        #pragma unroll
        for (int ks = 0; ks < 4; ks++) {
            int ch = ks * 2 + (quad >> 1);
            uint32_t a[4][4], b[2][4];
            #pragma unroll
            for (int mt = 0; mt < 4; mt++) {
                uint32_t ad = Ab + (uint32_t)(wm * 64 + mt * 16 + (quad & 1) * 8 + qr) * ROWB + ch * 16;
                LDMATRIX_X4(a[mt][0], a[mt][1], a[mt][2], a[mt][3], ad);
            }
            #pragma unroll
            for (int np = 0; np < 2; np++) {
                uint32_t ad = Bb + (uint32_t)(wn * 32 + np * 16 + (quad & 1) * 8 + qr) * ROWB + ch * 16;
                LDMATRIX_X4(b[np][0], b[np][1], b[np][2], b[np][3], ad);
            }
            #pragma unroll
            for (int mt = 0; mt < 4; mt++)
                #pragma unroll
                for (int nt = 0; nt < 4; nt++)
                    MMA16816(acc[mt][nt][0], acc[mt][nt][1], acc[mt][nt][2], acc[mt][nt][3],
                             a[mt][0], a[mt][1], a[mt][2], a[mt][3],
                             b[nt >> 1][nt & 1], b[nt >> 1][2 + (nt & 1)]);
        }
    }

    if (EPI == 3) {
        // ---- fused bias + LayerNorm(128) -> fp16 out (128 rows, guarded) ----
        float* sf = (float*)smem;   // [128][LNPAD]
        __syncthreads();
        #pragma unroll
        for (int mt = 0; mt < 4; mt++) {
            int lr0 = wm * 64 + mt * 16 + g;
            #pragma unroll
            for (int nt = 0; nt < 4; nt++) {
                int col = wn * 32 + nt * 8 + tig * 2;
                float bz0 = bias[col], bz1 = bias[col + 1];
                sf[lr0 * LNPAD + col]           = acc[mt][nt][0] + bz0;
                sf[lr0 * LNPAD + col + 1]       = acc[mt][nt][1] + bz1;
                sf[(lr0 + 8) * LNPAD + col]     = acc[mt][nt][2] + bz0;
                sf[(lr0 + 8) * LNPAD + col + 1] = acc[mt][nt][3] + bz1;
            }
        }
        __syncthreads();
        #pragma unroll
        for (int rr = 0; rr < 16; rr++) {
            int lr = wid * 16 + rr;
            int grow = bm + lr;
            float v[4];
            #pragma unroll
            for (int j = 0; j < 4; j++) v[j] = sf[lr * LNPAD + lane * 4 + j];
            float s1 = v[0] + v[1] + v[2] + v[3];
            float s2 = v[0]*v[0] + v[1]*v[1] + v[2]*v[2] + v[3]*v[3];
            #pragma unroll
            for (int o = 16; o > 0; o >>= 1) {
                s1 += __shfl_xor_sync(0xffffffffu, s1, o);
                s2 += __shfl_xor_sync(0xffffffffu, s2, o);
            }
            float mu = s1 * (1.f / 128.f);
            float rs = rsqrtf(s2 * (1.f / 128.f) - mu * mu + LN_EPS);
            if (grow < M) {
                #pragma unroll
                for (int j = 0; j < 2; j++) {
                    int c = lane * 4 + j * 2;
                    float o0 = (v[j * 2 + 0] - mu) * rs * lns[c]     + lnb[c];
                    float o1 = (v[j * 2 + 1] - mu) * rs * lns[c + 1] + lnb[c + 1];
                    *(__half2*)&Ch[(size_t)grow * C_DIM + c] = __floats2half2_rn(o0, o1);
                }
            }
        }
    } else {
        #pragma unroll
        for (int mt = 0; mt < 4; mt++) {
            int r0 = bm + wm * 64 + mt * 16 + g;
            int r1 = r0 + 8;
            #pragma unroll
            for (int nt = 0; nt < 4; nt++) {
                int col = bn + wn * 32 + nt * 8 + tig * 2;
                float bz0 = bias[col], bz1 = bias[col + 1];
                float v0 = acc[mt][nt][0] + bz0, v1 = acc[mt][nt][1] + bz1;
                float v2 = acc[mt][nt][2] + bz0, v3 = acc[mt][nt][3] + bz1;
                if (EPI == 1) {
                    v0 = gelu_exact(v0); v1 = gelu_exact(v1);
                    v2 = gelu_exact(v2); v3 = gelu_exact(v3);
                }
                if (EPI == 2) {
                    if (r0 < M) *(float2*)&Cf[(size_t)r0 * N + col] = make_float2(v0, v1);
                    if (r1 < M) *(float2*)&Cf[(size_t)r1 * N + col] = make_float2(v2, v3);
                } else {
                    if (r0 < M)
                        *(__half2*)&Ch[(size_t)r0 * N + col] = __floats2half2_rn(v0, v1);
                    if (r1 < M)
                        *(__half2*)&Ch[(size_t)r1 * N + col] = __floats2half2_rn(v2, v3);
                }
            }
        }
    }
}

// ---------------- launcher ----------------
extern "C" void kernel_launch(void* const* d_in, const int* in_sizes, int n_in,
                              void* d_out, int out_size) {
    (void)in_sizes; (void)n_in; (void)out_size;
    const float* x          = (const float*)d_in[0];
    const float* batched_x  = (const float*)d_in[1];
    const int*   indices    = (const int*)  d_in[2];
    const float* ln_d_scale = (const float*)d_in[3];
    const float* ln_d_bias  = (const float*)d_in[4];
    const float* W1_d       = (const float*)d_in[5];
    const float* b1_d       = (const float*)d_in[6];
    const float* W2_d       = (const float*)d_in[7];
    const float* b2_d       = (const float*)d_in[8];
    const float* ln_u_scale = (const float*)d_in[9];
    const float* ln_u_bias  = (const float*)d_in[10];
    const float* W1_u       = (const float*)d_in[11];
    const float* b1_u       = (const float*)d_in[12];
    const float* W2_u       = (const float*)d_in[13];
    const float* b2_u       = (const float*)d_in[14];
    float* out = (float*)d_out;

    __half *a0, *h1, *gg, *h2, *w1d, *w2d, *w1u, *w2u;
    cudaGetSymbolAddress((void**)&a0, g_A0);
    cudaGetSymbolAddress((void**)&h1, g_H1);
    cudaGetSymbolAddress((void**)&gg, g_G);
    cudaGetSymbolAddress((void**)&h2, g_H2);
    cudaGetSymbolAddress((void**)&w1d, g_w1d);
    cudaGetSymbolAddress((void**)&w2d, g_w2d);
    cudaGetSymbolAddress((void**)&w1u, g_w1u);
    cudaGetSymbolAddress((void**)&w2u, g_w2u);

    const int DYN = 3 * STG_BYTES;   // 110592
    cudaFuncSetAttribute(mma_gemm<1>, cudaFuncAttributeMaxDynamicSharedMemorySize, DYN);
    cudaFuncSetAttribute(mma_gemm<2>, cudaFuncAttributeMaxDynamicSharedMemorySize, DYN);
    cudaFuncSetAttribute(mma_gemm<3>, cudaFuncAttributeMaxDynamicSharedMemorySize, DYN);

    // 1) weights transpose+quantize AND head-clear, one launch
    k_prep_all<<<288 + CLR_BLKS, dim3(32, 8)>>>(W1_d, W2_d, W1_u, W2_u);
    // 2) build dup chains
    k_link<<<(ROWS + 255) / 256, 256>>>(indices);
    // 3) gather + dedup-sum + broadcast-add + LN(256) -> fp16 A0
    k_gather_ln<<<(ROWS + 7) / 8, 256>>>(x, batched_x, indices, ln_d_scale, ln_d_bias);

    // GEMM chain (fp16 single-pass, 128x128 blocks)
    mma_gemm<1><<<dim3(H_DIM / 128, MBLK128), 256, DYN>>>(a0, w1d, b1_d,
                                                          nullptr, nullptr,
                                                          h1, nullptr, ROWS, H_DIM, E_DIM);
    mma_gemm<3><<<dim3(1, MBLK128), 256, DYN>>>(h1, w2d, b2_d,
                                                ln_u_scale, ln_u_bias,
                                                gg, nullptr, ROWS, C_DIM, H_DIM);
    mma_gemm<1><<<dim3(U_DIM / 128, MBLK128), 256, DYN>>>(gg, w1u, b1_u,
                                                          nullptr, nullptr,
                                                          h2, nullptr, ROWS, U_DIM, C_DIM);
    mma_gemm<2><<<dim3(E_DIM / 128, MBLK128), 256, DYN>>>(h2, w2u, b2_u,
                                                          nullptr, nullptr,
                                                          nullptr, out, ROWS, E_DIM, U_DIM);
}